// round 15
// baseline (speedup 1.0000x reference)
#include <cuda_runtime.h>
#include <cuda_fp16.h>
#include <cstdint>

// ---------------- problem shapes (fixed) ----------------
#define N_ROWS 8192
#define M_ROWS 16384
#define DIM    256

#define BMT 64                      // tensor rows per CTA
#define BSC 12                      // scalar (FMA-pipe) rows per CTA
#define BM  (BMT + BSC)             // 76
#define GRIDX 108                   // ceil(8192/76)
#define ROWS_PAD (GRIDX * BM)       // 8208
#define BN 128
#define SPLITS 16
#define BROWS (M_ROWS / SPLITS)     // 1024
#define NBT   (BROWS / BN)          // 8 tiles
#define KCH   64                    // fp16 K per chunk (128B/row)
#define CPT   (DIM / KCH)           // 4
#define TOTCH (NBT * CPT)           // 32
#define NBUF  4

#define AW 128
#define BW 32
#define SCORE_STRIDE 136            // halves per score row (padded)
#define SCORE_HALVES (2 * BSC * SCORE_STRIDE)     // 3264 halves
#define SCORE_WORDS  (SCORE_HALVES / 2)           // 1632
#define A_WORDS (BM * AW)                          // 9728
#define B_WORDS (NBUF * BN * BW)                   // 16384
#define SMEM_WORDS (A_WORDS + B_WORDS + SCORE_WORDS)   // 27744
#define SMEM_BYTES (SMEM_WORDS * 4)                    // 110976 -> 2 CTAs/SM

// ---------------- scratch ----------------
__device__ float   g_An[N_ROWS * DIM];
__device__ __half  g_Ah[ROWS_PAD * DIM];
__device__ __half  g_Bh[M_ROWS * DIM];
__device__ float   g_partv[ROWS_PAD * SPLITS * 3];
__device__ int     g_parti[ROWS_PAD * SPLITS * 3];

// ---------------- helpers ----------------
__device__ __forceinline__ uint32_t smem_u32(const void* p) {
    uint32_t a;
    asm("{ .reg .u64 t; cvta.to.shared.u64 t, %1; cvt.u32.u64 %0, t; }" : "=r"(a) : "l"(p));
    return a;
}
__device__ __forceinline__ void cp_async16(uint32_t dst, const void* src) {
    asm volatile("cp.async.cg.shared.global [%0], [%1], 16;" :: "r"(dst), "l"(src));
}
#define CP_COMMIT()  asm volatile("cp.async.commit_group;" ::: "memory")
#define CP_WAIT(n)   asm volatile("cp.async.wait_group %0;" :: "n"(n) : "memory")

__device__ __forceinline__ void ldm_x4(uint32_t* r, uint32_t addr) {
    asm volatile("ldmatrix.sync.aligned.m8n8.x4.shared.b16 {%0,%1,%2,%3}, [%4];"
                 : "=r"(r[0]), "=r"(r[1]), "=r"(r[2]), "=r"(r[3]) : "r"(addr));
}
__device__ __forceinline__ void mma_f16(uint32_t* d, const uint32_t* a, const uint32_t* b) {
    asm volatile(
        "mma.sync.aligned.m16n8k16.row.col.f16.f16.f16.f16 "
        "{%0,%1},{%2,%3,%4,%5},{%6,%7},{%0,%1};"
        : "+r"(d[0]), "+r"(d[1])
        : "r"(a[0]), "r"(a[1]), "r"(a[2]), "r"(a[3]), "r"(b[0]), "r"(b[1]));
}
__device__ __forceinline__ __half2 u2h2(uint32_t u) { return *reinterpret_cast<__half2*>(&u); }

// ---------------- fused normalization: A rows [0,8208) then B rows ----------------
__global__ void normalize_all(const float* __restrict__ A, const float* __restrict__ B,
                              float* __restrict__ An, __half* __restrict__ Ah,
                              __half* __restrict__ Bh) {
    int blk = blockIdx.x, tid = threadIdx.x;
    if (blk < ROWS_PAD) {
        if (blk >= N_ROWS) { Ah[(size_t)blk * DIM + tid] = __float2half(0.0f); return; }
        float v = A[blk * DIM + tid];
        float s = v * v;
        #pragma unroll
        for (int o = 16; o > 0; o >>= 1) s += __shfl_xor_sync(0xFFFFFFFFu, s, o);
        __shared__ float red[8];
        if ((tid & 31) == 0) red[tid >> 5] = s;
        __syncthreads();
        __shared__ float tot;
        if (tid < 32) {
            float t = (tid < 8) ? red[tid] : 0.0f;
            #pragma unroll
            for (int o = 4; o > 0; o >>= 1) t += __shfl_xor_sync(0xFFFFFFFFu, t, o);
            if (tid == 0) tot = t;
        }
        __syncthreads();
        float y = v * rsqrtf(tot);
        An[blk * DIM + tid] = y;
        Ah[(size_t)blk * DIM + tid] = __float2half(y);
    } else {
        int row = blk - ROWS_PAD;
        float v = B[(size_t)row * DIM + tid];
        float s = v * v;
        #pragma unroll
        for (int o = 16; o > 0; o >>= 1) s += __shfl_xor_sync(0xFFFFFFFFu, s, o);
        __shared__ float red[8];
        if ((tid & 31) == 0) red[tid >> 5] = s;
        __syncthreads();
        __shared__ float tot;
        if (tid < 32) {
            float t = (tid < 8) ? red[tid] : 0.0f;
            #pragma unroll
            for (int o = 4; o > 0; o >>= 1) t += __shfl_xor_sync(0xFFFFFFFFu, t, o);
            if (tid == 0) tot = t;
        }
        __syncthreads();
        Bh[(size_t)row * DIM + tid] = __float2half(v * rsqrtf(tot));
    }
}

// ---------------- fp16 mma + HFMA2 hybrid GEMM + top-3 ----------------
__global__ void __launch_bounds__(256, 2)
gemm_top3(const __half* __restrict__ Ah, const __half* __restrict__ Bh,
          float* __restrict__ partv, int* __restrict__ parti) {
    extern __shared__ uint32_t smem[];
    uint32_t* sA = smem;
    uint32_t* sB = smem + A_WORDS;
    __half* scoreH = (__half*)(smem + A_WORDS + B_WORDS);
    const uint32_t sAu = smem_u32(sA);
    const uint32_t sBu = smem_u32(sB);

    const int tid  = threadIdx.x;
    const int w    = tid >> 5, lane = tid & 31;
    const int ty   = lane >> 2, tx = lane & 3;
    const int warpM = w >> 2, warpN = w & 3;      // 2 x 4 warp grid

    const int aBase = blockIdx.x * BM;
    const int bBase = blockIdx.y * BROWS;

    // ---- A tile: 76 rows x 256 fp16; word-swizzle ----
    for (int i = tid; i < BM * 32; i += 256) {          // 16B units
        int r = i >> 5, f = i & 31;
        uint32_t dw = (uint32_t)(r * AW + ((4 * f) ^ ((r & 7) << 2)));
        cp_async16(sAu + dw * 4, Ah + (size_t)(aBase + r) * DIM + f * 8);
    }
    CP_COMMIT();

    auto issueB = [&](int c) {
        int t = c >> 2, kc = c & 3, buf = c & 3;
        #pragma unroll 4
        for (int i = tid; i < BN * 8; i += 256) {       // 16B units
            int n = i >> 3, f = i & 7;
            uint32_t dw = (uint32_t)(buf * BN * BW + n * BW + ((4 * f) ^ ((n & 7) << 2)));
            cp_async16(sBu + dw * 4,
                       Bh + (size_t)(bBase + t * BN + n) * DIM + kc * KCH + f * 8);
        }
        CP_COMMIT();
    };

    issueB(0); issueB(1); issueB(2);

    // ---- tensor ldmatrix per-lane addresses ----
    uint32_t aAddrBase[2], aSw[2];
    {
        int rl = warpM * 32 + (lane & 15);
        #pragma unroll
        for (int m = 0; m < 2; m++) {
            int r = rl + m * 16;
            aAddrBase[m] = sAu + (uint32_t)(r * AW) * 4u;
            aSw[m] = (uint32_t)((r & 7) << 2);
        }
    }
    const uint32_t khA4 = (uint32_t)((lane >> 4) << 2);
    uint32_t bAddrBase[2], bSw[2];
    {
        int nl = warpN * 32 + ((lane >> 4) << 3) + (lane & 7);
        #pragma unroll
        for (int p = 0; p < 2; p++) {
            int n = nl + p * 16;
            bAddrBase[p] = (uint32_t)(n * BW) * 4u;
            bSw[p] = (uint32_t)((n & 7) << 2);
        }
    }
    const uint32_t khB4 = (uint32_t)(((lane >> 3) & 1) << 2);

    uint32_t acc[2][4][2];
    #pragma unroll
    for (int m = 0; m < 2; m++)
        #pragma unroll
        for (int nt = 0; nt < 4; nt++) { acc[m][nt][0] = 0u; acc[m][nt][1] = 0u; }

    // tensor-row top3
    float s0[4], s1[4], s2[4];
    int   i0[4], i1[4], i2[4];
    #pragma unroll
    for (int i = 0; i < 4; i++) {
        s0[i] = -2.0f; s1[i] = -2.0f; s2[i] = -2.0f;
        i0[i] = 0; i1[i] = 0; i2[i] = 0;
    }

    // scalar-path state: 6 rows per warp, 1 col per lane
    const int scol = warpN * 32 + lane;                 // B-local col 0..127
    const uint32_t swn = (uint32_t)((scol & 7) << 2);
    const uint32_t bRowW = (uint32_t)(scol * BW);
    __half2 sacc[6];
    #pragma unroll
    for (int r = 0; r < 6; r++) sacc[r] = __floats2half2_rn(0.0f, 0.0f);

    // scan-thread state (tid<192): top3 for scalar row tid>>4
    float ss0 = -2.0f, ss1 = -2.0f, ss2 = -2.0f;
    int   si0 = 0, si1 = 0, si2 = 0;
    const int scanRow = tid >> 4;            // 0..11 valid when tid<192
    const int scanC0  = (tid & 15) * 8;

    for (int c = 0; c < TOTCH; c++) {
        CP_WAIT(2);
        __syncthreads();

        // scan previous tile's scalar scores
        if ((c & 3) == 0 && c >= 4 && tid < 192) {
            int pt = (c >> 2) - 1;
            const __half* sc = scoreH + (pt & 1) * BSC * SCORE_STRIDE + scanRow * SCORE_STRIDE + scanC0;
            int colg = bBase + pt * BN + scanC0;
            float v[8];
            #pragma unroll
            for (int j = 0; j < 8; j++) v[j] = __half2float(sc[j]);
            float bm = v[0];
            #pragma unroll
            for (int j = 1; j < 8; j++) bm = fmaxf(bm, v[j]);
            if (bm > ss2) {
                #pragma unroll
                for (int j = 0; j < 8; j++) {
                    float x = v[j]; int ix = colg + j;
                    if (x > ss2) {
                        if (x > ss1) {
                            if (x > ss0) { ss2 = ss1; si2 = si1; ss1 = ss0; si1 = si0; ss0 = x; si0 = ix; }
                            else         { ss2 = ss1; si2 = si1; ss1 = x; si1 = ix; }
                        } else           { ss2 = x; si2 = ix; }
                    }
                }
            }
        }

        if (c + 3 < TOTCH) issueB(c + 3);
        else CP_COMMIT();

        const uint32_t cb32 = (uint32_t)((c & 3) * 32);
        const uint32_t bBufByte = sBu + (uint32_t)((c & 3) * BN * BW) * 4u;
        const uint32_t* sBc = sB + (c & 3) * BN * BW;

        // ---- tensor mma ----
        #pragma unroll
        for (int ks = 0; ks < 4; ks++) {
            const uint32_t ksw = (uint32_t)(ks * 8);
            uint32_t a[2][4];
            #pragma unroll
            for (int m = 0; m < 2; m++) {
                uint32_t woff = cb32 + ((ksw + khA4) ^ aSw[m]);
                ldm_x4(a[m], aAddrBase[m] + (woff << 2));
            }
            uint32_t bq[8];
            #pragma unroll
            for (int p = 0; p < 2; p++) {
                uint32_t woff = (ksw + khB4) ^ bSw[p];
                ldm_x4(&bq[p * 4], bBufByte + bAddrBase[p] + (woff << 2));
            }
            #pragma unroll
            for (int m = 0; m < 2; m++)
                #pragma unroll
                for (int nt = 0; nt < 4; nt++)
                    mma_f16(acc[m][nt], a[m], &bq[nt * 2]);
        }

        // ---- scalar HFMA2 rows ----
        #pragma unroll
        for (int h = 0; h < 4; h++) {
            const uint32_t f0w = (uint32_t)(8 * h);     // 4*f for f=2h
            uint4 b0 = *(const uint4*)(sBc + bRowW + ((f0w) ^ swn));
            uint4 b1 = *(const uint4*)(sBc + bRowW + ((f0w + 4) ^ swn));
            #pragma unroll
            for (int r = 0; r < 6; r++) {
                int ar = BMT + warpM * 6 + r;
                const uint32_t* aRow = sA + ar * AW + (c & 3) * 32;
                uint32_t asw = (uint32_t)((ar & 7) << 2);
                uint4 a0 = *(const uint4*)(aRow + ((f0w) ^ asw));
                uint4 a1 = *(const uint4*)(aRow + ((f0w + 4) ^ asw));
                sacc[r] = __hfma2(u2h2(a0.x), u2h2(b0.x), sacc[r]);
                sacc[r] = __hfma2(u2h2(a0.y), u2h2(b0.y), sacc[r]);
                sacc[r] = __hfma2(u2h2(a0.z), u2h2(b0.z), sacc[r]);
                sacc[r] = __hfma2(u2h2(a0.w), u2h2(b0.w), sacc[r]);
                sacc[r] = __hfma2(u2h2(a1.x), u2h2(b1.x), sacc[r]);
                sacc[r] = __hfma2(u2h2(a1.y), u2h2(b1.y), sacc[r]);
                sacc[r] = __hfma2(u2h2(a1.z), u2h2(b1.z), sacc[r]);
                sacc[r] = __hfma2(u2h2(a1.w), u2h2(b1.w), sacc[r]);
            }
        }

        if ((c & 3) == 3) {
            const int t = c >> 2;
            // scalar: dump scores + reset
            __half* sc = scoreH + (t & 1) * BSC * SCORE_STRIDE;
            #pragma unroll
            for (int r = 0; r < 6; r++) {
                float v = __half2float(__low2half(sacc[r])) + __half2float(__high2half(sacc[r]));
                sc[(warpM * 6 + r) * SCORE_STRIDE + scol] = __float2half(v);
                sacc[r] = __floats2half2_rn(0.0f, 0.0f);
            }
            // tensor: fold into top3 + reset
            const int tcol = bBase + t * BN + warpN * 32 + tx * 2;
            #pragma unroll
            for (int m = 0; m < 2; m++) {
                #pragma unroll
                for (int h = 0; h < 2; h++) {
                    const int sl = m * 2 + h;
                    float v[8];
                    #pragma unroll
                    for (int nt = 0; nt < 4; nt++) {
                        float2 f = __half22float2(*reinterpret_cast<const __half2*>(&acc[m][nt][h]));
                        v[nt * 2 + 0] = f.x;
                        v[nt * 2 + 1] = f.y;
                    }
                    float bm = v[0];
                    #pragma unroll
                    for (int q = 1; q < 8; q++) bm = fmaxf(bm, v[q]);
                    if (bm > s2[sl]) {
                        #pragma unroll
                        for (int nt = 0; nt < 4; nt++) {
                            #pragma unroll
                            for (int p = 0; p < 2; p++) {
                                float x = v[nt * 2 + p];
                                int col = tcol + nt * 8 + p;
                                if (x > s2[sl]) {
                                    if (x > s1[sl]) {
                                        if (x > s0[sl]) {
                                            s2[sl] = s1[sl]; i2[sl] = i1[sl];
                                            s1[sl] = s0[sl]; i1[sl] = i0[sl];
                                            s0[sl] = x;      i0[sl] = col;
                                        } else {
                                            s2[sl] = s1[sl]; i2[sl] = i1[sl];
                                            s1[sl] = x;      i1[sl] = col;
                                        }
                                    } else {
                                        s2[sl] = x; i2[sl] = col;
                                    }
                                }
                            }
                        }
                    }
                }
            }
            #pragma unroll
            for (int m = 0; m < 2; m++)
                #pragma unroll
                for (int nt = 0; nt < 4; nt++) { acc[m][nt][0] = 0u; acc[m][nt][1] = 0u; }
        }
    }

    // ---- final scalar-score scan (tile NBT-1) ----
    __syncthreads();
    if (tid < 192) {
        int pt = NBT - 1;
        const __half* sc = scoreH + (pt & 1) * BSC * SCORE_STRIDE + scanRow * SCORE_STRIDE + scanC0;
        int colg = bBase + pt * BN + scanC0;
        #pragma unroll
        for (int j = 0; j < 8; j++) {
            float x = __half2float(sc[j]); int ix = colg + j;
            if (x > ss2) {
                if (x > ss1) {
                    if (x > ss0) { ss2 = ss1; si2 = si1; ss1 = ss0; si1 = si0; ss0 = x; si0 = ix; }
                    else         { ss2 = ss1; si2 = si1; ss1 = x; si1 = ix; }
                } else           { ss2 = x; si2 = ix; }
            }
        }
    }
    __syncthreads();

    // ---- unified CTA merge: every row (tensor + scalar) has 16 contributors ----
    float* candV = (float*)smem;                 // [76][16][3]
    int*   candI = (int*)smem + BM * 16 * 3;     // [76][16][3]
    #pragma unroll
    for (int m = 0; m < 2; m++) {
        #pragma unroll
        for (int h = 0; h < 2; h++) {
            const int sl = m * 2 + h;
            int row = warpM * 32 + m * 16 + h * 8 + ty;
            int ct  = warpN * 4 + tx;
            int o = (row * 16 + ct) * 3;
            candV[o + 0] = s0[sl]; candV[o + 1] = s1[sl]; candV[o + 2] = s2[sl];
            candI[o + 0] = i0[sl]; candI[o + 1] = i1[sl]; candI[o + 2] = i2[sl];
        }
    }
    if (tid < 192) {
        int o = ((BMT + scanRow) * 16 + (tid & 15)) * 3;
        candV[o + 0] = ss0; candV[o + 1] = ss1; candV[o + 2] = ss2;
        candI[o + 0] = si0; candI[o + 1] = si1; candI[o + 2] = si2;
    }
    __syncthreads();
    if (tid < BM) {
        const float* pv = candV + tid * 48;
        const int*   pi = candI + tid * 48;
        float t0 = -2.0f, t1 = -2.0f, t2 = -2.0f;
        int   j0 = 0, j1 = 0, j2 = 0;
        #pragma unroll
        for (int i = 0; i < 48; i++) {
            float v = pv[i]; int ix = pi[i];
            if (v > t2) {
                if (v > t1) {
                    if (v > t0) { t2 = t1; j2 = j1; t1 = t0; j1 = j0; t0 = v; j0 = ix; }
                    else        { t2 = t1; j2 = j1; t1 = v;  j1 = ix; }
                } else          { t2 = v; j2 = ix; }
            }
        }
        size_t row = (size_t)(aBase + tid);
        size_t o = (row * SPLITS + blockIdx.y) * 3;
        partv[o + 0] = t0; partv[o + 1] = t1; partv[o + 2] = t2;
        parti[o + 0] = j0; parti[o + 1] = j1; parti[o + 2] = j2;
    }
}

// ---------------- final: top-8 of 48 candidates, exact fp32 rescore, mean top-3 ----
__device__ __forceinline__ unsigned long long mk_key(float v, int idx) {
    uint32_t u = __float_as_uint(v);
    u = (u & 0x80000000u) ? ~u : (u | 0x80000000u);
    return ((unsigned long long)u << 32) | (uint32_t)idx;
}

__global__ void rescore_top3(const float* __restrict__ partv, const int* __restrict__ parti,
                             const float* __restrict__ An, const float* __restrict__ Braw,
                             float* __restrict__ out) {
    const int warp = (blockIdx.x * blockDim.x + threadIdx.x) >> 5;
    const int lane = threadIdx.x & 31;
    if (warp >= N_ROWS) return;
    const int row = warp;

    const float* pv = partv + (size_t)row * 48;
    const int*   pi = parti + (size_t)row * 48;
    unsigned long long k0 = mk_key(pv[lane], pi[lane]);
    unsigned long long k1 = (lane < 16) ? mk_key(pv[32 + lane], pi[32 + lane]) : 0ull;

    int win[8];
    #pragma unroll
    for (int r = 0; r < 8; r++) {
        unsigned long long m = (k0 > k1) ? k0 : k1;
        #pragma unroll
        for (int o = 16; o > 0; o >>= 1) {
            unsigned long long t = __shfl_xor_sync(0xFFFFFFFFu, m, o);
            if (t > m) m = t;
        }
        win[r] = (int)(uint32_t)m;
        if (k0 == m) k0 = 0ull;
        if (k1 == m) k1 = 0ull;
    }

    const float4* a4 = (const float4*)(An + (size_t)row * DIM);
    float4 av0 = a4[lane * 2], av1 = a4[lane * 2 + 1];

    float dots[8];
    #pragma unroll
    for (int j = 0; j < 8; j++) {
        const float4* b4 = (const float4*)(Braw + (size_t)win[j] * DIM);
        float4 b0 = b4[lane * 2], b1 = b4[lane * 2 + 1];
        float p = av0.x * b0.x + av0.y * b0.y + av0.z * b0.z + av0.w * b0.w
                + av1.x * b1.x + av1.y * b1.y + av1.z * b1.z + av1.w * b1.w;
        float q = b0.x * b0.x + b0.y * b0.y + b0.z * b0.z + b0.w * b0.w
                + b1.x * b1.x + b1.y * b1.y + b1.z * b1.z + b1.w * b1.w;
        #pragma unroll
        for (int o = 16; o > 0; o >>= 1) {
            p += __shfl_xor_sync(0xFFFFFFFFu, p, o);
            q += __shfl_xor_sync(0xFFFFFFFFu, q, o);
        }
        dots[j] = p * rsqrtf(q);
    }

    if (lane == 0) {
        float t0 = -2.0f, t1 = -2.0f, t2 = -2.0f;
        #pragma unroll
        for (int j = 0; j < 8; j++) {
            float v = dots[j];
            t2 = fmaxf(t2, fminf(v, t1));
            t1 = fmaxf(t1, fminf(v, t0));
            t0 = fmaxf(t0, v);
        }
        out[row] = (t0 + t1 + t2) * (1.0f / 3.0f);
    }
}

// ---------------- launcher ----------------
extern "C" void kernel_launch(void* const* d_in, const int* in_sizes, int n_in,
                              void* d_out, int out_size) {
    const float* A = (const float*)d_in[0];
    const float* B = (const float*)d_in[1];
    float* out = (float*)d_out;

    float* An;  cudaGetSymbolAddress((void**)&An,  g_An);
    __half* Ah; cudaGetSymbolAddress((void**)&Ah, g_Ah);
    __half* Bh; cudaGetSymbolAddress((void**)&Bh, g_Bh);
    float* pv;  cudaGetSymbolAddress((void**)&pv, g_partv);
    int*   pi;  cudaGetSymbolAddress((void**)&pi, g_parti);

    cudaFuncSetAttribute(gemm_top3, cudaFuncAttributeMaxDynamicSharedMemorySize, SMEM_BYTES);

    normalize_all<<<ROWS_PAD + M_ROWS, DIM>>>(A, B, An, Ah, Bh);

    dim3 grid(GRIDX, SPLITS);
    gemm_top3<<<grid, 256, SMEM_BYTES>>>(Ah, Bh, pv, pi);

    rescore_top3<<<N_ROWS * 32 / 256, 256>>>(pv, pi, An, B, out);
}

// round 16
// speedup vs baseline: 1.7442x; 1.7442x over previous
#include <cuda_runtime.h>
#include <cuda_fp16.h>
#include <cstdint>

// ---------------- problem shapes (fixed) ----------------
#define N_ROWS 8192
#define M_ROWS 16384
#define DIM    256

#define BM 64
#define BN 256
#define SPLITS 16
#define BROWS (M_ROWS / SPLITS)     // 1024
#define NBT   (BROWS / BN)          // 4 tiles
#define KCH   64                    // fp16 K-elems per chunk (128B/row)
#define CPT   (DIM / KCH)           // 4 chunks per tile
#define TOTCH (NBT * CPT)           // 16
#define NBUF  2

// smem (uint32 words): A = 64 x 128 (32KB); B = 2 bufs x 256 rows x 32 words (64KB)
#define AW 128
#define BW 32
#define SMEM_WORDS (BM * AW + NBUF * BN * BW)   // 8192 + 16384 = 24576
#define SMEM_BYTES (SMEM_WORDS * 4)             // 98304 -> 2 CTAs/SM

// ---------------- scratch ----------------
__device__ float   g_An[N_ROWS * DIM];          // normalized A (fp32, for exact rescore)
__device__ __half  g_Ah[N_ROWS * DIM];
__device__ __half  g_Bh[M_ROWS * DIM];
__device__ float   g_partv[N_ROWS * SPLITS * 3];
__device__ int     g_parti[N_ROWS * SPLITS * 3];

// ---------------- helpers ----------------
__device__ __forceinline__ uint32_t smem_u32(const void* p) {
    uint32_t a;
    asm("{ .reg .u64 t; cvta.to.shared.u64 t, %1; cvt.u32.u64 %0, t; }" : "=r"(a) : "l"(p));
    return a;
}
__device__ __forceinline__ void cp_async16(uint32_t dst, const void* src) {
    asm volatile("cp.async.cg.shared.global [%0], [%1], 16;" :: "r"(dst), "l"(src));
}
#define CP_COMMIT()  asm volatile("cp.async.commit_group;" ::: "memory")
#define CP_WAIT(n)   asm volatile("cp.async.wait_group %0;" :: "n"(n) : "memory")

__device__ __forceinline__ void ldm_x4(uint32_t* r, uint32_t addr) {
    asm volatile("ldmatrix.sync.aligned.m8n8.x4.shared.b16 {%0,%1,%2,%3}, [%4];"
                 : "=r"(r[0]), "=r"(r[1]), "=r"(r[2]), "=r"(r[3]) : "r"(addr));
}
__device__ __forceinline__ void mma_f16(uint32_t* d, const uint32_t* a, const uint32_t* b) {
    asm volatile(
        "mma.sync.aligned.m16n8k16.row.col.f16.f16.f16.f16 "
        "{%0,%1},{%2,%3,%4,%5},{%6,%7},{%0,%1};"
        : "+r"(d[0]), "+r"(d[1])
        : "r"(a[0]), "r"(a[1]), "r"(a[2]), "r"(a[3]), "r"(b[0]), "r"(b[1]));
}

// ---------------- row L2 normalization ----------------
__global__ void normalize_rows_full(const float* __restrict__ in,
                                    float* __restrict__ outf,
                                    __half* __restrict__ outh) {
    int row = blockIdx.x, tid = threadIdx.x;
    float v = in[row * DIM + tid];
    float s = v * v;
    #pragma unroll
    for (int o = 16; o > 0; o >>= 1) s += __shfl_xor_sync(0xFFFFFFFFu, s, o);
    __shared__ float red[8];
    if ((tid & 31) == 0) red[tid >> 5] = s;
    __syncthreads();
    __shared__ float tot;
    if (tid < 32) {
        float t = (tid < 8) ? red[tid] : 0.0f;
        #pragma unroll
        for (int o = 4; o > 0; o >>= 1) t += __shfl_xor_sync(0xFFFFFFFFu, t, o);
        if (tid == 0) tot = t;
    }
    __syncthreads();
    float y = v * rsqrtf(tot);
    outf[row * DIM + tid] = y;
    outh[row * DIM + tid] = __float2half(y);
}

__global__ void normalize_rows_h(const float* __restrict__ in,
                                 __half* __restrict__ outh) {
    int row = blockIdx.x, tid = threadIdx.x;
    float v = in[row * DIM + tid];
    float s = v * v;
    #pragma unroll
    for (int o = 16; o > 0; o >>= 1) s += __shfl_xor_sync(0xFFFFFFFFu, s, o);
    __shared__ float red[8];
    if ((tid & 31) == 0) red[tid >> 5] = s;
    __syncthreads();
    __shared__ float tot;
    if (tid < 32) {
        float t = (tid < 8) ? red[tid] : 0.0f;
        #pragma unroll
        for (int o = 4; o > 0; o >>= 1) t += __shfl_xor_sync(0xFFFFFFFFu, t, o);
        if (tid == 0) tot = t;
    }
    __syncthreads();
    outh[row * DIM + tid] = __float2half(v * rsqrtf(tot));
}

// ---------------- fp16 mma GEMM (fp16 acc, BN=256, occ=2) + top-3 ----------------
__global__ void __launch_bounds__(256, 2)
gemm_top3(const __half* __restrict__ Ah, const __half* __restrict__ Bh,
          float* __restrict__ partv, int* __restrict__ parti) {
    extern __shared__ uint32_t smem[];
    uint32_t* sA = smem;
    uint32_t* sB = smem + BM * AW;
    const uint32_t sAu = smem_u32(sA);
    const uint32_t sBu = smem_u32(sB);

    const int tid  = threadIdx.x;
    const int w    = tid >> 5, lane = tid & 31;
    const int ty   = lane >> 2, tx = lane & 3;
    const int warpM = w >> 2, warpN = w & 3;      // 2 x 4 warp grid; warpN owns 64 cols

    const int aBase = blockIdx.x * BM;
    const int bBase = blockIdx.y * BROWS;

    // ---- A tile: 64 rows x 256 fp16; word-swizzle iw' = iw ^ ((r&7)<<2) ----
    #pragma unroll 4
    for (int i = tid; i < BM * 32; i += 256) {          // 16B units
        int r = i >> 5, f = i & 31;
        uint32_t dw = (uint32_t)(r * AW + ((4 * f) ^ ((r & 7) << 2)));
        cp_async16(sAu + dw * 4, Ah + (size_t)(aBase + r) * DIM + f * 8);
    }
    CP_COMMIT();

    auto issueB = [&](int c) {
        int t = c >> 2, kc = c & 3, buf = c & 1;
        #pragma unroll 8
        for (int i = tid; i < BN * 8; i += 256) {       // 2048 16B units
            int n = i >> 3, f = i & 7;
            uint32_t dw = (uint32_t)(buf * BN * BW + n * BW + ((4 * f) ^ ((n & 7) << 2)));
            cp_async16(sBu + dw * 4,
                       Bh + (size_t)(bBase + t * BN + n) * DIM + kc * KCH + f * 8);
        }
        CP_COMMIT();
    };

    issueB(0); issueB(1);

    // ---- precompute ldmatrix per-lane addresses ----
    uint32_t aAddrBase[2], aSw[2];
    {
        int rl = warpM * 32 + (lane & 15);
        #pragma unroll
        for (int m = 0; m < 2; m++) {
            int r = rl + m * 16;
            aAddrBase[m] = sAu + (uint32_t)(r * AW) * 4u;
            aSw[m] = (uint32_t)((r & 7) << 2);
        }
    }
    const uint32_t khA4 = (uint32_t)((lane >> 4) << 2);
    uint32_t bAddrBase[4], bSw[4];
    {
        int nl = warpN * 64 + ((lane >> 4) << 3) + (lane & 7);
        #pragma unroll
        for (int p = 0; p < 4; p++) {
            int n = nl + p * 16;
            bAddrBase[p] = (uint32_t)(n * BW) * 4u;
            bSw[p] = (uint32_t)((n & 7) << 2);
        }
    }
    const uint32_t khB4 = (uint32_t)(((lane >> 3) & 1) << 2);

    uint32_t acc[2][8][2];                         // fp16x2 accumulators, 8 nt tiles
    #pragma unroll
    for (int m = 0; m < 2; m++)
        #pragma unroll
        for (int nt = 0; nt < 8; nt++) { acc[m][nt][0] = 0u; acc[m][nt][1] = 0u; }

    float s0[4], s1[4], s2[4];
    int   i0[4], i1[4], i2[4];
    #pragma unroll
    for (int i = 0; i < 4; i++) {
        s0[i] = -2.0f; s1[i] = -2.0f; s2[i] = -2.0f;
        i0[i] = 0; i1[i] = 0; i2[i] = 0;
    }

    for (int c = 0; c < TOTCH; c++) {
        CP_WAIT(1);                  // group c complete (c+1 may be in flight)
        __syncthreads();

        const uint32_t cb32 = (uint32_t)((c & 3) * 32);
        const uint32_t bBufByte = sBu + (uint32_t)((c & 1) * BN * BW) * 4u;

        #pragma unroll
        for (int ks = 0; ks < 4; ks++) {
            const uint32_t ksw = (uint32_t)(ks * 8);
            uint32_t a[2][4];
            #pragma unroll
            for (int m = 0; m < 2; m++) {
                uint32_t woff = cb32 + ((ksw + khA4) ^ aSw[m]);
                ldm_x4(a[m], aAddrBase[m] + (woff << 2));
            }
            uint32_t bq[16];
            #pragma unroll
            for (int p = 0; p < 4; p++) {
                uint32_t woff = (ksw + khB4) ^ bSw[p];
                ldm_x4(&bq[p * 4], bBufByte + bAddrBase[p] + (woff << 2));
            }
            #pragma unroll
            for (int m = 0; m < 2; m++)
                #pragma unroll
                for (int nt = 0; nt < 8; nt++)
                    mma_f16(acc[m][nt], a[m], &bq[nt * 2]);
        }

        __syncthreads();             // all warps done reading buf (c&1)
        if (c + 2 < TOTCH) issueB(c + 2);

        if ((c & 3) == 3) {
            const int tcol = bBase + (c >> 2) * BN + warpN * 64 + tx * 2;
            #pragma unroll
            for (int m = 0; m < 2; m++) {
                #pragma unroll
                for (int h = 0; h < 2; h++) {
                    const int sl = m * 2 + h;
                    float v[16];
                    #pragma unroll
                    for (int nt = 0; nt < 8; nt++) {
                        float2 f = __half22float2(*reinterpret_cast<const __half2*>(&acc[m][nt][h]));
                        v[nt * 2 + 0] = f.x;
                        v[nt * 2 + 1] = f.y;
                    }
                    float bm = v[0];
                    #pragma unroll
                    for (int q = 1; q < 16; q++) bm = fmaxf(bm, v[q]);
                    if (bm > s2[sl]) {
                        #pragma unroll
                        for (int nt = 0; nt < 8; nt++) {
                            #pragma unroll
                            for (int p = 0; p < 2; p++) {
                                float x = v[nt * 2 + p];
                                int col = tcol + nt * 8 + p;
                                if (x > s2[sl]) {
                                    if (x > s1[sl]) {
                                        if (x > s0[sl]) {
                                            s2[sl] = s1[sl]; i2[sl] = i1[sl];
                                            s1[sl] = s0[sl]; i1[sl] = i0[sl];
                                            s0[sl] = x;      i0[sl] = col;
                                        } else {
                                            s2[sl] = s1[sl]; i2[sl] = i1[sl];
                                            s1[sl] = x;      i1[sl] = col;
                                        }
                                    } else {
                                        s2[sl] = x; i2[sl] = col;
                                    }
                                }
                            }
                        }
                    }
                }
            }
            #pragma unroll
            for (int m = 0; m < 2; m++)
                #pragma unroll
                for (int nt = 0; nt < 8; nt++) { acc[m][nt][0] = 0u; acc[m][nt][1] = 0u; }
        }
    }

    // ---- CTA-level merge: 16 contributors per row -> top-3 (val+idx) ----
    __syncthreads();
    float* candV = (float*)smem;                 // [64][16][3]
    int*   candI = (int*)(smem + 3072);          // [64][16][3]
    #pragma unroll
    for (int m = 0; m < 2; m++) {
        #pragma unroll
        for (int h = 0; h < 2; h++) {
            const int sl = m * 2 + h;
            int row = warpM * 32 + m * 16 + h * 8 + ty;
            int ct  = warpN * 4 + tx;
            int o = (row * 16 + ct) * 3;
            candV[o + 0] = s0[sl]; candV[o + 1] = s1[sl]; candV[o + 2] = s2[sl];
            candI[o + 0] = i0[sl]; candI[o + 1] = i1[sl]; candI[o + 2] = i2[sl];
        }
    }
    __syncthreads();
    if (tid < BM) {
        const float* pv = candV + tid * 48;
        const int*   pi = candI + tid * 48;
        float t0 = -2.0f, t1 = -2.0f, t2 = -2.0f;
        int   j0 = 0, j1 = 0, j2 = 0;
        #pragma unroll
        for (int i = 0; i < 48; i++) {
            float v = pv[i]; int ix = pi[i];
            if (v > t2) {
                if (v > t1) {
                    if (v > t0) { t2 = t1; j2 = j1; t1 = t0; j1 = j0; t0 = v; j0 = ix; }
                    else        { t2 = t1; j2 = j1; t1 = v;  j1 = ix; }
                } else          { t2 = v; j2 = ix; }
            }
        }
        size_t row = (size_t)(blockIdx.x * BM + tid);
        size_t o = (row * SPLITS + blockIdx.y) * 3;
        partv[o + 0] = t0; partv[o + 1] = t1; partv[o + 2] = t2;
        parti[o + 0] = j0; parti[o + 1] = j1; parti[o + 2] = j2;
    }
}

// ---------------- final: top-8 of 48 candidates, exact fp32 rescore, mean top-3 ----
__device__ __forceinline__ unsigned long long mk_key(float v, int idx) {
    uint32_t u = __float_as_uint(v);
    u = (u & 0x80000000u) ? ~u : (u | 0x80000000u);
    return ((unsigned long long)u << 32) | (uint32_t)idx;
}

__global__ void rescore_top3(const float* __restrict__ partv, const int* __restrict__ parti,
                             const float* __restrict__ An, const float* __restrict__ Braw,
                             float* __restrict__ out) {
    const int warp = (blockIdx.x * blockDim.x + threadIdx.x) >> 5;
    const int lane = threadIdx.x & 31;
    if (warp >= N_ROWS) return;
    const int row = warp;

    const float* pv = partv + (size_t)row * 48;
    const int*   pi = parti + (size_t)row * 48;
    unsigned long long k0 = mk_key(pv[lane], pi[lane]);
    unsigned long long k1 = (lane < 16) ? mk_key(pv[32 + lane], pi[32 + lane]) : 0ull;

    int win[8];
    #pragma unroll
    for (int r = 0; r < 8; r++) {
        unsigned long long m = (k0 > k1) ? k0 : k1;
        #pragma unroll
        for (int o = 16; o > 0; o >>= 1) {
            unsigned long long t = __shfl_xor_sync(0xFFFFFFFFu, m, o);
            if (t > m) m = t;
        }
        win[r] = (int)(uint32_t)m;
        if (k0 == m) k0 = 0ull;
        if (k1 == m) k1 = 0ull;
    }

    const float4* a4 = (const float4*)(An + (size_t)row * DIM);
    float4 av0 = a4[lane * 2], av1 = a4[lane * 2 + 1];

    float dots[8];
    #pragma unroll
    for (int j = 0; j < 8; j++) {
        const float4* b4 = (const float4*)(Braw + (size_t)win[j] * DIM);
        float4 b0 = b4[lane * 2], b1 = b4[lane * 2 + 1];
        float p = av0.x * b0.x + av0.y * b0.y + av0.z * b0.z + av0.w * b0.w
                + av1.x * b1.x + av1.y * b1.y + av1.z * b1.z + av1.w * b1.w;
        float q = b0.x * b0.x + b0.y * b0.y + b0.z * b0.z + b0.w * b0.w
                + b1.x * b1.x + b1.y * b1.y + b1.z * b1.z + b1.w * b1.w;
        #pragma unroll
        for (int o = 16; o > 0; o >>= 1) {
            p += __shfl_xor_sync(0xFFFFFFFFu, p, o);
            q += __shfl_xor_sync(0xFFFFFFFFu, q, o);
        }
        dots[j] = p * rsqrtf(q);
    }

    if (lane == 0) {
        float t0 = -2.0f, t1 = -2.0f, t2 = -2.0f;
        #pragma unroll
        for (int j = 0; j < 8; j++) {
            float v = dots[j];
            t2 = fmaxf(t2, fminf(v, t1));
            t1 = fmaxf(t1, fminf(v, t0));
            t0 = fmaxf(t0, v);
        }
        out[row] = (t0 + t1 + t2) * (1.0f / 3.0f);
    }
}

// ---------------- launcher ----------------
extern "C" void kernel_launch(void* const* d_in, const int* in_sizes, int n_in,
                              void* d_out, int out_size) {
    const float* A = (const float*)d_in[0];
    const float* B = (const float*)d_in[1];
    float* out = (float*)d_out;

    float* An;  cudaGetSymbolAddress((void**)&An,  g_An);
    __half* Ah; cudaGetSymbolAddress((void**)&Ah, g_Ah);
    __half* Bh; cudaGetSymbolAddress((void**)&Bh, g_Bh);
    float* pv;  cudaGetSymbolAddress((void**)&pv, g_partv);
    int*   pi;  cudaGetSymbolAddress((void**)&pi, g_parti);

    cudaFuncSetAttribute(gemm_top3, cudaFuncAttributeMaxDynamicSharedMemorySize, SMEM_BYTES);

    normalize_rows_full<<<N_ROWS, DIM>>>(A, An, Ah);
    normalize_rows_h<<<M_ROWS, DIM>>>(B, Bh);

    dim3 grid(N_ROWS / BM, SPLITS);
    gemm_top3<<<grid, 256, SMEM_BYTES>>>(Ah, Bh, pv, pi);

    rescore_top3<<<N_ROWS * 32 / 256, 256>>>(pv, pi, An, B, out);
}

// round 17
// speedup vs baseline: 1.7494x; 1.0030x over previous
#include <cuda_runtime.h>
#include <cuda_fp16.h>
#include <cstdint>

// ---------------- problem shapes (fixed) ----------------
#define N_ROWS 8192
#define M_ROWS 16384
#define DIM    256

#define BM 64
#define BN 256
#define SPLITS 16
#define BROWS (M_ROWS / SPLITS)     // 1024
#define NBT   (BROWS / BN)          // 4 tiles
#define KCH   64                    // fp16 K-elems per chunk (128B/row)
#define CPT   (DIM / KCH)           // 4 chunks per tile
#define TOTCH (NBT * CPT)           // 16
#define NBUF  2

// smem (uint32 words): A = 64 x 128 (32KB); B = 2 bufs x 256 rows x 32 words (64KB)
#define AW 128
#define BW 32
#define SMEM_WORDS (BM * AW + NBUF * BN * BW)   // 24576
#define SMEM_BYTES (SMEM_WORDS * 4)             // 98304 -> 2 CTAs/SM

// ---------------- scratch ----------------
__device__ __half  g_Ah[N_ROWS * DIM];
__device__ __half  g_Bh[M_ROWS * DIM];
__device__ float   g_partv[N_ROWS * SPLITS * 3];
__device__ int     g_parti[N_ROWS * SPLITS * 3];

// ---------------- helpers ----------------
__device__ __forceinline__ uint32_t smem_u32(const void* p) {
    uint32_t a;
    asm("{ .reg .u64 t; cvta.to.shared.u64 t, %1; cvt.u32.u64 %0, t; }" : "=r"(a) : "l"(p));
    return a;
}
__device__ __forceinline__ void cp_async16(uint32_t dst, const void* src) {
    asm volatile("cp.async.cg.shared.global [%0], [%1], 16;" :: "r"(dst), "l"(src));
}
#define CP_COMMIT()  asm volatile("cp.async.commit_group;" ::: "memory")
#define CP_WAIT(n)   asm volatile("cp.async.wait_group %0;" :: "n"(n) : "memory")

__device__ __forceinline__ void ldm_x4(uint32_t* r, uint32_t addr) {
    asm volatile("ldmatrix.sync.aligned.m8n8.x4.shared.b16 {%0,%1,%2,%3}, [%4];"
                 : "=r"(r[0]), "=r"(r[1]), "=r"(r[2]), "=r"(r[3]) : "r"(addr));
}
__device__ __forceinline__ void mma_f16(uint32_t* d, const uint32_t* a, const uint32_t* b) {
    asm volatile(
        "mma.sync.aligned.m16n8k16.row.col.f16.f16.f16.f16 "
        "{%0,%1},{%2,%3,%4,%5},{%6,%7},{%0,%1};"
        : "+r"(d[0]), "+r"(d[1])
        : "r"(a[0]), "r"(a[1]), "r"(a[2]), "r"(a[3]), "r"(b[0]), "r"(b[1]));
}

// ---------------- fused row L2 normalization (A then B), fp16 out only ----------------
__global__ void normalize_all(const float* __restrict__ A, const float* __restrict__ B,
                              __half* __restrict__ Ah, __half* __restrict__ Bh) {
    int blk = blockIdx.x, tid = threadIdx.x;
    const float* src = (blk < N_ROWS) ? (A + (size_t)blk * DIM)
                                      : (B + (size_t)(blk - N_ROWS) * DIM);
    __half* dst = (blk < N_ROWS) ? (Ah + (size_t)blk * DIM)
                                 : (Bh + (size_t)(blk - N_ROWS) * DIM);
    float v = src[tid];
    float s = v * v;
    #pragma unroll
    for (int o = 16; o > 0; o >>= 1) s += __shfl_xor_sync(0xFFFFFFFFu, s, o);
    __shared__ float red[8];
    if ((tid & 31) == 0) red[tid >> 5] = s;
    __syncthreads();
    __shared__ float tot;
    if (tid < 32) {
        float t = (tid < 8) ? red[tid] : 0.0f;
        #pragma unroll
        for (int o = 4; o > 0; o >>= 1) t += __shfl_xor_sync(0xFFFFFFFFu, t, o);
        if (tid == 0) tot = t;
    }
    __syncthreads();
    dst[tid] = __float2half(v * rsqrtf(tot));
}

// ---------------- fp16 mma GEMM (fp16 acc, BN=256, occ=2) + top-3 ----------------
__global__ void __launch_bounds__(256, 2)
gemm_top3(const __half* __restrict__ Ah, const __half* __restrict__ Bh,
          float* __restrict__ partv, int* __restrict__ parti) {
    extern __shared__ uint32_t smem[];
    uint32_t* sA = smem;
    uint32_t* sB = smem + BM * AW;
    const uint32_t sAu = smem_u32(sA);
    const uint32_t sBu = smem_u32(sB);

    const int tid  = threadIdx.x;
    const int w    = tid >> 5, lane = tid & 31;
    const int ty   = lane >> 2, tx = lane & 3;
    const int warpM = w >> 2, warpN = w & 3;      // 2 x 4 warp grid; warpN owns 64 cols

    const int aBase = blockIdx.x * BM;
    const int bBase = blockIdx.y * BROWS;

    // ---- A tile: 64 rows x 256 fp16; word-swizzle iw' = iw ^ ((r&7)<<2) ----
    #pragma unroll 4
    for (int i = tid; i < BM * 32; i += 256) {          // 16B units
        int r = i >> 5, f = i & 31;
        uint32_t dw = (uint32_t)(r * AW + ((4 * f) ^ ((r & 7) << 2)));
        cp_async16(sAu + dw * 4, Ah + (size_t)(aBase + r) * DIM + f * 8);
    }
    CP_COMMIT();

    auto issueB = [&](int c) {
        int t = c >> 2, kc = c & 3, buf = c & 1;
        #pragma unroll 8
        for (int i = tid; i < BN * 8; i += 256) {       // 2048 16B units
            int n = i >> 3, f = i & 7;
            uint32_t dw = (uint32_t)(buf * BN * BW + n * BW + ((4 * f) ^ ((n & 7) << 2)));
            cp_async16(sBu + dw * 4,
                       Bh + (size_t)(bBase + t * BN + n) * DIM + kc * KCH + f * 8);
        }
        CP_COMMIT();
    };

    issueB(0); issueB(1);

    // ---- precompute ldmatrix per-lane addresses ----
    uint32_t aAddrBase[2], aSw[2];
    {
        int rl = warpM * 32 + (lane & 15);
        #pragma unroll
        for (int m = 0; m < 2; m++) {
            int r = rl + m * 16;
            aAddrBase[m] = sAu + (uint32_t)(r * AW) * 4u;
            aSw[m] = (uint32_t)((r & 7) << 2);
        }
    }
    const uint32_t khA4 = (uint32_t)((lane >> 4) << 2);
    uint32_t bAddrBase[4], bSw[4];
    {
        int nl = warpN * 64 + ((lane >> 4) << 3) + (lane & 7);
        #pragma unroll
        for (int p = 0; p < 4; p++) {
            int n = nl + p * 16;
            bAddrBase[p] = (uint32_t)(n * BW) * 4u;
            bSw[p] = (uint32_t)((n & 7) << 2);
        }
    }
    const uint32_t khB4 = (uint32_t)(((lane >> 3) & 1) << 2);

    uint32_t acc[2][8][2];                         // fp16x2 accumulators, 8 nt tiles
    #pragma unroll
    for (int m = 0; m < 2; m++)
        #pragma unroll
        for (int nt = 0; nt < 8; nt++) { acc[m][nt][0] = 0u; acc[m][nt][1] = 0u; }

    float s0[4], s1[4], s2[4];
    int   i0[4], i1[4], i2[4];
    #pragma unroll
    for (int i = 0; i < 4; i++) {
        s0[i] = -2.0f; s1[i] = -2.0f; s2[i] = -2.0f;
        i0[i] = 0; i1[i] = 0; i2[i] = 0;
    }

    for (int c = 0; c < TOTCH; c++) {
        CP_WAIT(1);                  // group c complete (c+1 may be in flight)
        __syncthreads();

        const uint32_t cb32 = (uint32_t)((c & 3) * 32);
        const uint32_t bBufByte = sBu + (uint32_t)((c & 1) * BN * BW) * 4u;

        #pragma unroll
        for (int ks = 0; ks < 4; ks++) {
            const uint32_t ksw = (uint32_t)(ks * 8);
            uint32_t a[2][4];
            #pragma unroll
            for (int m = 0; m < 2; m++) {
                uint32_t woff = cb32 + ((ksw + khA4) ^ aSw[m]);
                ldm_x4(a[m], aAddrBase[m] + (woff << 2));
            }
            uint32_t bq[16];
            #pragma unroll
            for (int p = 0; p < 4; p++) {
                uint32_t woff = (ksw + khB4) ^ bSw[p];
                ldm_x4(&bq[p * 4], bBufByte + bAddrBase[p] + (woff << 2));
            }
            #pragma unroll
            for (int m = 0; m < 2; m++)
                #pragma unroll
                for (int nt = 0; nt < 8; nt++)
                    mma_f16(acc[m][nt], a[m], &bq[nt * 2]);
        }

        __syncthreads();             // all warps done reading buf (c&1)
        if (c + 2 < TOTCH) issueB(c + 2);

        if ((c & 3) == 3) {
            const int tcol = bBase + (c >> 2) * BN + warpN * 64 + tx * 2;
            #pragma unroll
            for (int m = 0; m < 2; m++) {
                #pragma unroll
                for (int h = 0; h < 2; h++) {
                    const int sl = m * 2 + h;
                    float v[16];
                    #pragma unroll
                    for (int nt = 0; nt < 8; nt++) {
                        float2 f = __half22float2(*reinterpret_cast<const __half2*>(&acc[m][nt][h]));
                        v[nt * 2 + 0] = f.x;
                        v[nt * 2 + 1] = f.y;
                    }
                    float bm = v[0];
                    #pragma unroll
                    for (int q = 1; q < 16; q++) bm = fmaxf(bm, v[q]);
                    if (bm > s2[sl]) {
                        #pragma unroll
                        for (int nt = 0; nt < 8; nt++) {
                            #pragma unroll
                            for (int p = 0; p < 2; p++) {
                                float x = v[nt * 2 + p];
                                int col = tcol + nt * 8 + p;
                                if (x > s2[sl]) {
                                    if (x > s1[sl]) {
                                        if (x > s0[sl]) {
                                            s2[sl] = s1[sl]; i2[sl] = i1[sl];
                                            s1[sl] = s0[sl]; i1[sl] = i0[sl];
                                            s0[sl] = x;      i0[sl] = col;
                                        } else {
                                            s2[sl] = s1[sl]; i2[sl] = i1[sl];
                                            s1[sl] = x;      i1[sl] = col;
                                        }
                                    } else {
                                        s2[sl] = x; i2[sl] = col;
                                    }
                                }
                            }
                        }
                    }
                }
            }
            #pragma unroll
            for (int m = 0; m < 2; m++)
                #pragma unroll
                for (int nt = 0; nt < 8; nt++) { acc[m][nt][0] = 0u; acc[m][nt][1] = 0u; }
        }
    }

    // ---- CTA-level merge: 16 contributors per row -> top-3 (val+idx) ----
    __syncthreads();
    float* candV = (float*)smem;                 // [64][16][3]
    int*   candI = (int*)(smem + 3072);          // [64][16][3]
    #pragma unroll
    for (int m = 0; m < 2; m++) {
        #pragma unroll
        for (int h = 0; h < 2; h++) {
            const int sl = m * 2 + h;
            int row = warpM * 32 + m * 16 + h * 8 + ty;
            int ct  = warpN * 4 + tx;
            int o = (row * 16 + ct) * 3;
            candV[o + 0] = s0[sl]; candV[o + 1] = s1[sl]; candV[o + 2] = s2[sl];
            candI[o + 0] = i0[sl]; candI[o + 1] = i1[sl]; candI[o + 2] = i2[sl];
        }
    }
    __syncthreads();
    if (tid < BM) {
        const float* pv = candV + tid * 48;
        const int*   pi = candI + tid * 48;
        float t0 = -2.0f, t1 = -2.0f, t2 = -2.0f;
        int   j0 = 0, j1 = 0, j2 = 0;
        #pragma unroll
        for (int i = 0; i < 48; i++) {
            float v = pv[i]; int ix = pi[i];
            if (v > t2) {
                if (v > t1) {
                    if (v > t0) { t2 = t1; j2 = j1; t1 = t0; j1 = j0; t0 = v; j0 = ix; }
                    else        { t2 = t1; j2 = j1; t1 = v;  j1 = ix; }
                } else          { t2 = v; j2 = ix; }
            }
        }
        size_t row = (size_t)(blockIdx.x * BM + tid);
        size_t o = (row * SPLITS + blockIdx.y) * 3;
        partv[o + 0] = t0; partv[o + 1] = t1; partv[o + 2] = t2;
        parti[o + 0] = j0; parti[o + 1] = j1; parti[o + 2] = j2;
    }
}

// ---------------- final: top-8 of 48 candidates, exact fp32 rescore, mean top-3 ----
__device__ __forceinline__ unsigned long long mk_key(float v, int idx) {
    uint32_t u = __float_as_uint(v);
    u = (u & 0x80000000u) ? ~u : (u | 0x80000000u);
    return ((unsigned long long)u << 32) | (uint32_t)idx;
}

__global__ void rescore_top3(const float* __restrict__ partv, const int* __restrict__ parti,
                             const float* __restrict__ Araw, const float* __restrict__ Braw,
                             float* __restrict__ out) {
    const int warp = (blockIdx.x * blockDim.x + threadIdx.x) >> 5;
    const int lane = threadIdx.x & 31;
    if (warp >= N_ROWS) return;
    const int row = warp;

    const float* pv = partv + (size_t)row * 48;
    const int*   pi = parti + (size_t)row * 48;
    unsigned long long k0 = mk_key(pv[lane], pi[lane]);
    unsigned long long k1 = (lane < 16) ? mk_key(pv[32 + lane], pi[32 + lane]) : 0ull;

    int win[8];
    #pragma unroll
    for (int r = 0; r < 8; r++) {
        unsigned long long m = (k0 > k1) ? k0 : k1;
        #pragma unroll
        for (int o = 16; o > 0; o >>= 1) {
            unsigned long long t = __shfl_xor_sync(0xFFFFFFFFu, m, o);
            if (t > m) m = t;
        }
        win[r] = (int)(uint32_t)m;
        if (k0 == m) k0 = 0ull;
        if (k1 == m) k1 = 0ull;
    }

    const float4* a4 = (const float4*)(Araw + (size_t)row * DIM);
    float4 av0 = a4[lane * 2], av1 = a4[lane * 2 + 1];

    // |a|^2 once
    float qa = av0.x * av0.x + av0.y * av0.y + av0.z * av0.z + av0.w * av0.w
             + av1.x * av1.x + av1.y * av1.y + av1.z * av1.z + av1.w * av1.w;
    #pragma unroll
    for (int o = 16; o > 0; o >>= 1) qa += __shfl_xor_sync(0xFFFFFFFFu, qa, o);
    const float ra = rsqrtf(qa);

    float dots[8];
    #pragma unroll
    for (int j = 0; j < 8; j++) {
        const float4* b4 = (const float4*)(Braw + (size_t)win[j] * DIM);
        float4 b0 = b4[lane * 2], b1 = b4[lane * 2 + 1];
        float p = av0.x * b0.x + av0.y * b0.y + av0.z * b0.z + av0.w * b0.w
                + av1.x * b1.x + av1.y * b1.y + av1.z * b1.z + av1.w * b1.w;
        float q = b0.x * b0.x + b0.y * b0.y + b0.z * b0.z + b0.w * b0.w
                + b1.x * b1.x + b1.y * b1.y + b1.z * b1.z + b1.w * b1.w;
        #pragma unroll
        for (int o = 16; o > 0; o >>= 1) {
            p += __shfl_xor_sync(0xFFFFFFFFu, p, o);
            q += __shfl_xor_sync(0xFFFFFFFFu, q, o);
        }
        dots[j] = p * ra * rsqrtf(q);
    }

    if (lane == 0) {
        float t0 = -2.0f, t1 = -2.0f, t2 = -2.0f;
        #pragma unroll
        for (int j = 0; j < 8; j++) {
            float v = dots[j];
            t2 = fmaxf(t2, fminf(v, t1));
            t1 = fmaxf(t1, fminf(v, t0));
            t0 = fmaxf(t0, v);
        }
        out[row] = (t0 + t1 + t2) * (1.0f / 3.0f);
    }
}

// ---------------- launcher ----------------
extern "C" void kernel_launch(void* const* d_in, const int* in_sizes, int n_in,
                              void* d_out, int out_size) {
    const float* A = (const float*)d_in[0];
    const float* B = (const float*)d_in[1];
    float* out = (float*)d_out;

    __half* Ah; cudaGetSymbolAddress((void**)&Ah, g_Ah);
    __half* Bh; cudaGetSymbolAddress((void**)&Bh, g_Bh);
    float* pv;  cudaGetSymbolAddress((void**)&pv, g_partv);
    int*   pi;  cudaGetSymbolAddress((void**)&pi, g_parti);

    cudaFuncSetAttribute(gemm_top3, cudaFuncAttributeMaxDynamicSharedMemorySize, SMEM_BYTES);

    normalize_all<<<N_ROWS + M_ROWS, DIM>>>(A, B, Ah, Bh);

    dim3 grid(N_ROWS / BM, SPLITS);
    gemm_top3<<<grid, 256, SMEM_BYTES>>>(Ah, Bh, pv, pi);

    rescore_top3<<<N_ROWS * 32 / 256, 256>>>(pv, pi, A, B, out);
}